// round 1
// baseline (speedup 1.0000x reference)
#include <cuda_runtime.h>
#include <cuda_bf16.h>
#include <cstdint>
#include <cstddef>

// ---------------- Problem constants ----------------
#define S_LEN 2048
#define HDIM  2048
#define NH    16
#define NOPE  128
#define ROPE  64
#define VHD   128
#define QHD   192      // NOPE + ROPE
#define QLR   1536
#define KVLR  512
#define FF    8192
#define EPS_F 1e-6f
static __device__ __host__ __forceinline__ float scale_const() { return 0.07216878364870323f; } // 192^-0.5

// ---------------- Scratch (__device__ globals; no allocation allowed) ----------------
__device__ float g_xn  [S_LEN * HDIM];        // rms(hidden)
__device__ float g_qlat[S_LEN * QLR];         // x@wq_a (and its rms, in place)
__device__ float g_q   [S_LEN * NH * QHD];    // q (rope applied in place)
__device__ float g_ckv [S_LEN * (KVLR+ROPE)]; // x@wkv_a
__device__ float g_ckvn[S_LEN * KVLR];        // rms of ckv[:, :512]
__device__ float g_kpe [S_LEN * ROPE];        // roped k_pe
__device__ float g_kv  [S_LEN * NH * (NOPE+VHD)]; // ckvn@wkv_b
__device__ float g_ao  [S_LEN * NH * VHD];    // attention output
__device__ float g_h2  [S_LEN * HDIM];        // hidden after attn residual
__device__ float g_y   [S_LEN * HDIM];        // rms(h2)
__device__ float g_g   [S_LEN * FF];          // gate (then silu*up in place)
__device__ float g_u   [S_LEN * FF];          // up

// ---------------- RMSNorm: one block per row ----------------
__global__ __launch_bounds__(256) void rms_kernel(
    const float* __restrict__ in, const float* __restrict__ w,
    float* __restrict__ out, int cols, int in_stride, int out_stride)
{
    int row = blockIdx.x;
    const float* ip = in + (size_t)row * in_stride;
    float ss = 0.f;
    for (int i = threadIdx.x; i < cols; i += 256) { float v = ip[i]; ss = fmaf(v, v, ss); }
    __shared__ float sh[8];
    int lane = threadIdx.x & 31, wid = threadIdx.x >> 5;
    #pragma unroll
    for (int o = 16; o > 0; o >>= 1) ss += __shfl_xor_sync(0xffffffffu, ss, o);
    if (lane == 0) sh[wid] = ss;
    __syncthreads();
    float tot = 0.f;
    #pragma unroll
    for (int i = 0; i < 8; i++) tot += sh[i];
    float r = rsqrtf(tot / (float)cols + EPS_F);
    float* op = out + (size_t)row * out_stride;
    for (int i = threadIdx.x; i < cols; i += 256) op[i] = ip[i] * r * w[i];
}

// ---------------- Tiled SGEMM: C[M,N] = A[M,K] @ B[K,N] (+ Res) ----------------
// BM=BN=128, BK=8, 256 threads, 8x8 microtile. M % 128 == 0, K % 8 == 0, N % 4 == 0.
__global__ __launch_bounds__(256) void sgemm_kernel(
    const float* __restrict__ A, const float* __restrict__ B,
    const float* __restrict__ Res, float* __restrict__ C,
    int M, int N, int K)
{
    __shared__ float As[8][128];
    __shared__ float Bs[8][128];
    const int tid = threadIdx.x;
    const int row0 = blockIdx.y * 128;
    const int col0 = blockIdx.x * 128;
    const int tRow = tid >> 4;         // 0..15
    const int tCol = tid & 15;         // 0..15
    const int aRow = tid >> 1;         // 0..127
    const int aCol = (tid & 1) * 4;    // 0 or 4
    const int bRow = tid >> 5;         // 0..7
    const int bCol = (tid & 31) * 4;   // 0..124

    float acc[8][8];
    #pragma unroll
    for (int i = 0; i < 8; i++)
        #pragma unroll
        for (int j = 0; j < 8; j++) acc[i][j] = 0.f;

    const bool bInRange = (col0 + bCol) < N;

    for (int k0 = 0; k0 < K; k0 += 8) {
        float4 av = *reinterpret_cast<const float4*>(A + (size_t)(row0 + aRow) * K + k0 + aCol);
        As[aCol + 0][aRow] = av.x;
        As[aCol + 1][aRow] = av.y;
        As[aCol + 2][aRow] = av.z;
        As[aCol + 3][aRow] = av.w;
        float4 bv = make_float4(0.f, 0.f, 0.f, 0.f);
        if (bInRange)
            bv = *reinterpret_cast<const float4*>(B + (size_t)(k0 + bRow) * N + col0 + bCol);
        *reinterpret_cast<float4*>(&Bs[bRow][bCol]) = bv;
        __syncthreads();

        #pragma unroll
        for (int k = 0; k < 8; k++) {
            float regM[8], regN[8];
            #pragma unroll
            for (int i = 0; i < 8; i++) regM[i] = As[k][tRow * 8 + i];
            #pragma unroll
            for (int j = 0; j < 8; j++) regN[j] = Bs[k][tCol * 8 + j];
            #pragma unroll
            for (int i = 0; i < 8; i++)
                #pragma unroll
                for (int j = 0; j < 8; j++)
                    acc[i][j] = fmaf(regM[i], regN[j], acc[i][j]);
        }
        __syncthreads();
    }

    #pragma unroll
    for (int i = 0; i < 8; i++) {
        int r = row0 + tRow * 8 + i;
        #pragma unroll
        for (int j = 0; j < 8; j += 4) {
            int c = col0 + tCol * 8 + j;
            if (c < N) {
                float4 v = make_float4(acc[i][j], acc[i][j+1], acc[i][j+2], acc[i][j+3]);
                if (Res) {
                    float4 rv = *reinterpret_cast<const float4*>(Res + (size_t)r * N + c);
                    v.x += rv.x; v.y += rv.y; v.z += rv.z; v.w += rv.w;
                }
                *reinterpret_cast<float4*>(C + (size_t)r * N + c) = v;
            }
        }
    }
}

// ---------------- RoPE (interleaved: reference permutes even/odd first) ----------------
// q layout: [S, NH*192], pe part at offset h*192+128, dim 64. One warp per (s,h).
__global__ void rope_q_kernel(float* __restrict__ q,
                              const float* __restrict__ cosb, const float* __restrict__ sinb,
                              const int* __restrict__ pos)
{
    int s = blockIdx.x, h = blockIdx.y, j = threadIdx.x;  // j in [0,32)
    int p = pos[s];
    float* base = q + (size_t)s * (NH * QHD) + h * QHD + NOPE;
    float x0 = base[2 * j], x1 = base[2 * j + 1];
    float c0 = cosb[p * ROPE + j],      s0 = sinb[p * ROPE + j];
    float c1 = cosb[p * ROPE + 32 + j], s1 = sinb[p * ROPE + 32 + j];
    __syncwarp();
    base[j]      = x0 * c0 - x1 * s0;
    base[32 + j] = x1 * c1 + x0 * s1;
}

__global__ void rope_k_kernel(const float* __restrict__ ckv, float* __restrict__ kpe,
                              const float* __restrict__ cosb, const float* __restrict__ sinb,
                              const int* __restrict__ pos)
{
    int s = blockIdx.x, j = threadIdx.x;  // j in [0,32)
    int p = pos[s];
    const float* base = ckv + (size_t)s * (KVLR + ROPE) + KVLR;
    float x0 = base[2 * j], x1 = base[2 * j + 1];
    kpe[(size_t)s * ROPE + j]      = x0 * cosb[p * ROPE + j]      - x1 * sinb[p * ROPE + j];
    kpe[(size_t)s * ROPE + 32 + j] = x1 * cosb[p * ROPE + 32 + j] + x0 * sinb[p * ROPE + 32 + j];
}

// ---------------- Causal flash attention (fp32) ----------------
// grid (S/16, NH), 256 threads. Each thread owns (qi, ki) = (tid/16, tid%16),
// accumulates dims [ki*8, ki*8+8) of V for query row qi.
#define KSTR 196
__global__ __launch_bounds__(256) void attn_kernel(
    const float* __restrict__ Q,   // [S, NH*192]
    const float* __restrict__ KV,  // [S, NH*256] (k_nope | v)
    const float* __restrict__ KPE, // [S, 64]
    float* __restrict__ O)         // [S, NH*128]
{
    __shared__ float sQ[16][KSTR];
    __shared__ float sK[16][KSTR];
    __shared__ float sV[16][132];
    __shared__ float sS[16][17];

    const int h  = blockIdx.y;
    const int q0 = blockIdx.x * 16;
    const int tid = threadIdx.x;
    const int qi = tid >> 4, ki = tid & 15;
    const float sc = scale_const();

    // load + scale Q tile (192 dims, 48 float4 per row)
    for (int idx = tid; idx < 16 * 48; idx += 256) {
        int r = idx / 48, c = idx % 48;
        float4 v = *reinterpret_cast<const float4*>(Q + (size_t)(q0 + r) * (NH * QHD) + h * QHD + c * 4);
        v.x *= sc; v.y *= sc; v.z *= sc; v.w *= sc;
        *reinterpret_cast<float4*>(&sQ[r][c * 4]) = v;
    }
    float m = -1e30f, l = 0.f, acc[8];
    #pragma unroll
    for (int i = 0; i < 8; i++) acc[i] = 0.f;
    __syncthreads();

    for (int k0 = 0; k0 < q0 + 16; k0 += 16) {
        // K tile: 128 nope from KV + 64 pe from KPE
        for (int idx = tid; idx < 16 * 48; idx += 256) {
            int r = idx / 48, c = idx % 48;
            float4 v;
            if (c < 32)
                v = *reinterpret_cast<const float4*>(KV + (size_t)(k0 + r) * (NH * 256) + h * 256 + c * 4);
            else
                v = *reinterpret_cast<const float4*>(KPE + (size_t)(k0 + r) * ROPE + (c - 32) * 4);
            *reinterpret_cast<float4*>(&sK[r][c * 4]) = v;
        }
        // V tile
        for (int idx = tid; idx < 16 * 32; idx += 256) {
            int r = idx / 32, c = idx % 32;
            *reinterpret_cast<float4*>(&sV[r][c * 4]) =
                *reinterpret_cast<const float4*>(KV + (size_t)(k0 + r) * (NH * 256) + h * 256 + 128 + c * 4);
        }
        __syncthreads();

        // one score per thread
        float s = 0.f;
        const float4* qp = reinterpret_cast<const float4*>(sQ[qi]);
        const float4* kp = reinterpret_cast<const float4*>(sK[ki]);
        #pragma unroll
        for (int d = 0; d < 48; d++) {
            float4 a = qp[d], b = kp[d];
            s = fmaf(a.x, b.x, s); s = fmaf(a.y, b.y, s);
            s = fmaf(a.z, b.z, s); s = fmaf(a.w, b.w, s);
        }
        if (k0 + ki > q0 + qi) s = -1e30f;
        sS[qi][ki] = s;
        __syncthreads();

        // online softmax (replicated across the 16 threads of a row)
        float tmax = -1e30f;
        #pragma unroll
        for (int k = 0; k < 16; k++) tmax = fmaxf(tmax, sS[qi][k]);
        float mnew  = fmaxf(m, tmax);
        float alpha = __expf(m - mnew);
        float pk[16], psum = 0.f;
        #pragma unroll
        for (int k = 0; k < 16; k++) { pk[k] = __expf(sS[qi][k] - mnew); psum += pk[k]; }
        l = l * alpha + psum;
        m = mnew;
        #pragma unroll
        for (int i = 0; i < 8; i++) acc[i] *= alpha;
        #pragma unroll
        for (int k = 0; k < 16; k++) {
            float p = pk[k];
            #pragma unroll
            for (int i = 0; i < 8; i++)
                acc[i] = fmaf(p, sV[k][ki * 8 + i], acc[i]);
        }
        __syncthreads();
    }

    float invl = 1.0f / l;
    #pragma unroll
    for (int i = 0; i < 8; i++)
        O[(size_t)(q0 + qi) * (NH * VHD) + h * VHD + ki * 8 + i] = acc[i] * invl;
}

// ---------------- SiLU(g) * u, in place into g ----------------
__global__ void silu_mul_kernel(float* __restrict__ g, const float* __restrict__ u, int n4)
{
    for (int i = blockIdx.x * blockDim.x + threadIdx.x; i < n4; i += gridDim.x * blockDim.x) {
        float4 a = reinterpret_cast<float4*>(g)[i];
        float4 b = reinterpret_cast<const float4*>(u)[i];
        a.x = (a.x / (1.f + __expf(-a.x))) * b.x;
        a.y = (a.y / (1.f + __expf(-a.y))) * b.y;
        a.z = (a.z / (1.f + __expf(-a.z))) * b.z;
        a.w = (a.w / (1.f + __expf(-a.w))) * b.w;
        reinterpret_cast<float4*>(g)[i] = a;
    }
}

// ---------------- Host orchestration ----------------
static void gemm(const float* A, const float* B, const float* Res, float* C, int M, int N, int K)
{
    dim3 grid((N + 127) / 128, (M + 127) / 128);
    sgemm_kernel<<<grid, 256>>>(A, B, Res, C, M, N, K);
}

extern "C" void kernel_launch(void* const* d_in, const int* in_sizes, int n_in,
                              void* d_out, int out_size)
{
    const float* hidden  = (const float*)d_in[0];
    const float* sinb    = (const float*)d_in[1];
    const float* cosb    = (const float*)d_in[2];
    const float* wq_a    = (const float*)d_in[3];
    const float* q_a_ln  = (const float*)d_in[4];
    const float* wq_b    = (const float*)d_in[5];
    const float* wkv_a   = (const float*)d_in[6];
    const float* kv_a_ln = (const float*)d_in[7];
    const float* wkv_b   = (const float*)d_in[8];
    const float* wo      = (const float*)d_in[9];
    const float* in_ln   = (const float*)d_in[10];
    const float* post_ln = (const float*)d_in[11];
    const float* w_gate  = (const float*)d_in[12];
    const float* w_up    = (const float*)d_in[13];
    const float* w_down  = (const float*)d_in[14];
    const int*   pos     = (const int*)d_in[15];
    float* out = (float*)d_out;

    float *xn, *qlat, *qb, *ckv, *ckvn, *kpe, *kv, *ao, *h2, *y, *gb, *ub;
    cudaGetSymbolAddress((void**)&xn,   g_xn);
    cudaGetSymbolAddress((void**)&qlat, g_qlat);
    cudaGetSymbolAddress((void**)&qb,   g_q);
    cudaGetSymbolAddress((void**)&ckv,  g_ckv);
    cudaGetSymbolAddress((void**)&ckvn, g_ckvn);
    cudaGetSymbolAddress((void**)&kpe,  g_kpe);
    cudaGetSymbolAddress((void**)&kv,   g_kv);
    cudaGetSymbolAddress((void**)&ao,   g_ao);
    cudaGetSymbolAddress((void**)&h2,   g_h2);
    cudaGetSymbolAddress((void**)&y,    g_y);
    cudaGetSymbolAddress((void**)&gb,   g_g);
    cudaGetSymbolAddress((void**)&ub,   g_u);

    // 1) input RMSNorm
    rms_kernel<<<S_LEN, 256>>>(hidden, in_ln, xn, HDIM, HDIM, HDIM);
    // 2) q low-rank path
    gemm(xn, wq_a, nullptr, qlat, S_LEN, QLR, HDIM);
    rms_kernel<<<S_LEN, 256>>>(qlat, q_a_ln, qlat, QLR, QLR, QLR);
    gemm(qlat, wq_b, nullptr, qb, S_LEN, NH * QHD, QLR);
    // 3) kv low-rank path
    gemm(xn, wkv_a, nullptr, ckv, S_LEN, KVLR + ROPE, HDIM);
    rms_kernel<<<S_LEN, 256>>>(ckv, kv_a_ln, ckvn, KVLR, KVLR + ROPE, KVLR);
    rope_k_kernel<<<S_LEN, 32>>>(ckv, kpe, cosb, sinb, pos);
    gemm(ckvn, wkv_b, nullptr, kv, S_LEN, NH * (NOPE + VHD), KVLR);
    // 4) rope on q_pe (in place)
    rope_q_kernel<<<dim3(S_LEN, NH), 32>>>(qb, cosb, sinb, pos);
    // 5) attention
    attn_kernel<<<dim3(S_LEN / 16, NH), 256>>>(qb, kv, kpe, ao);
    // 6) output projection + residual
    gemm(ao, wo, hidden, h2, S_LEN, HDIM, NH * VHD);
    // 7) MLP
    rms_kernel<<<S_LEN, 256>>>(h2, post_ln, y, HDIM, HDIM, HDIM);
    gemm(y, w_gate, nullptr, gb, S_LEN, FF, HDIM);
    gemm(y, w_up,   nullptr, ub, S_LEN, FF, HDIM);
    silu_mul_kernel<<<4096, 256>>>(gb, ub, (S_LEN * FF) / 4);
    gemm(gb, w_down, h2, out, S_LEN, HDIM, FF);
}

// round 4
// speedup vs baseline: 1.9521x; 1.9521x over previous
#include <cuda_runtime.h>
#include <cuda_bf16.h>
#include <cstdint>
#include <cstddef>

// ---------------- Problem constants ----------------
#define S_LEN 2048
#define HDIM  2048
#define NH    16
#define NOPE  128
#define ROPE  64
#define VHD   128
#define QHD   192      // NOPE + ROPE
#define QLR   1536
#define KVLR  512
#define FF    8192
#define EPS_F 1e-6f
static __device__ __host__ __forceinline__ float scale_const() { return 0.07216878364870323f; } // 192^-0.5

// ---------------- Scratch (__device__ globals; no allocation allowed) ----------------
__device__ float g_xn  [S_LEN * HDIM];        // rms(hidden)
__device__ float g_qlat[S_LEN * QLR];         // x@wq_a (and its rms, in place)
__device__ float g_q   [S_LEN * NH * QHD];    // q (rope applied in place)
__device__ float g_ckv [S_LEN * (KVLR+ROPE)]; // x@wkv_a
__device__ float g_ckvn[S_LEN * KVLR];        // rms of ckv[:, :512]
__device__ float g_kpe [S_LEN * ROPE];        // roped k_pe
__device__ float g_kv  [S_LEN * NH * (NOPE+VHD)]; // ckvn@wkv_b
__device__ float g_ao  [S_LEN * NH * VHD];    // attention output
__device__ float g_h2  [S_LEN * HDIM];        // hidden after attn residual
__device__ float g_y   [S_LEN * HDIM];        // rms(h2)
__device__ float g_g   [S_LEN * FF];          // gate (then silu*up in place)
__device__ float g_u   [S_LEN * FF];          // up

// ---------------- RMSNorm: one block per row ----------------
__global__ __launch_bounds__(256) void rms_kernel(
    const float* __restrict__ in, const float* __restrict__ w,
    float* __restrict__ out, int cols, int in_stride, int out_stride)
{
    int row = blockIdx.x;
    const float* ip = in + (size_t)row * in_stride;
    float ss = 0.f;
    for (int i = threadIdx.x; i < cols; i += 256) { float v = ip[i]; ss = fmaf(v, v, ss); }
    __shared__ float sh[8];
    int lane = threadIdx.x & 31, wid = threadIdx.x >> 5;
    #pragma unroll
    for (int o = 16; o > 0; o >>= 1) ss += __shfl_xor_sync(0xffffffffu, ss, o);
    if (lane == 0) sh[wid] = ss;
    __syncthreads();
    float tot = 0.f;
    #pragma unroll
    for (int i = 0; i < 8; i++) tot += sh[i];
    float r = rsqrtf(tot / (float)cols + EPS_F);
    float* op = out + (size_t)row * out_stride;
    for (int i = threadIdx.x; i < cols; i += 256) op[i] = ip[i] * r * w[i];
}

// ---------------- Tensor-core GEMM (bf16 3-split, fp32 accumulate) ----------------
// C[M,N] = A[M,K] @ B[K,N] (+ Res). M%128==0, K%32==0, N%4==0.
// BM=BN=128, BK=32, 256 threads, warp tile 64x32, double-buffered smem.
#define BM   128
#define BN   128
#define BKC  32
#define ASTR 40     // padded bf16 stride for A rows (bank-group conflict-free ldmatrix)
#define BSTR 136    // padded bf16 stride for B rows
#define GEMM_SMEM_BYTES ((4*BM*ASTR + 4*BKC*BSTR) * 2)   // 75776 bytes

static __device__ __forceinline__ uint32_t smem_u32(const void* p) {
    return (uint32_t)__cvta_generic_to_shared(p);
}
static __device__ __forceinline__ void ldsm_x4(uint32_t* r, uint32_t addr) {
    asm volatile("ldmatrix.sync.aligned.m8n8.x4.shared.b16 {%0,%1,%2,%3}, [%4];"
                 : "=r"(r[0]), "=r"(r[1]), "=r"(r[2]), "=r"(r[3]) : "r"(addr));
}
static __device__ __forceinline__ void ldsm_x4_t(uint32_t* r, uint32_t addr) {
    asm volatile("ldmatrix.sync.aligned.m8n8.x4.trans.shared.b16 {%0,%1,%2,%3}, [%4];"
                 : "=r"(r[0]), "=r"(r[1]), "=r"(r[2]), "=r"(r[3]) : "r"(addr));
}
static __device__ __forceinline__ void mma16816(float* c, const uint32_t* a, const uint32_t* b) {
    asm volatile("mma.sync.aligned.m16n8k16.row.col.f32.bf16.bf16.f32 "
                 "{%0,%1,%2,%3}, {%4,%5,%6,%7}, {%8,%9}, {%0,%1,%2,%3};"
                 : "+f"(c[0]), "+f"(c[1]), "+f"(c[2]), "+f"(c[3])
                 : "r"(a[0]), "r"(a[1]), "r"(a[2]), "r"(a[3]), "r"(b[0]), "r"(b[1]));
}

__global__ __launch_bounds__(256, 1) void mma_gemm_kernel(
    const float* __restrict__ A, const float* __restrict__ B,
    const float* __restrict__ Res, float* __restrict__ C,
    int M, int N, int K)
{
    extern __shared__ __nv_bfloat16 smbuf[];
    __nv_bfloat16* sAh = smbuf;
    __nv_bfloat16* sAl = sAh + 2 * BM * ASTR;
    __nv_bfloat16* sBh = sAl + 2 * BM * ASTR;
    __nv_bfloat16* sBl = sBh + 2 * BKC * BSTR;

    const int tid  = threadIdx.x;
    const int lane = tid & 31;
    const int warp = tid >> 5;
    const int wm0  = (warp >> 2) * 64;   // 0 or 64
    const int wn0  = (warp & 3) * 32;    // 0,32,64,96
    const int row0 = blockIdx.y * BM;
    const int col0 = blockIdx.x * BN;

    // staging assignment: 4 float4 per thread for A and B
    int aR[4], aC[4], bR[4], bC[4];
    bool bval[4];
    #pragma unroll
    for (int i = 0; i < 4; i++) {
        int lin = tid + 256 * i;
        aR[i] = lin >> 3;  aC[i] = (lin & 7) * 4;
        bR[i] = lin >> 5;  bC[i] = (lin & 31) * 4;
        bval[i] = (col0 + bC[i]) < N;
    }

    const uint32_t sAh_u = smem_u32(sAh), sAl_u = smem_u32(sAl);
    const uint32_t sBh_u = smem_u32(sBh), sBl_u = smem_u32(sBl);
    const uint32_t aLane = (uint32_t)(((lane & 15) * ASTR + (lane >> 4) * 8) * 2);
    const uint32_t bLane = (uint32_t)(((lane & 15) * BSTR + (lane >> 4) * 8) * 2);

    float acc[4][4][4];
    #pragma unroll
    for (int mi = 0; mi < 4; mi++)
        #pragma unroll
        for (int ni = 0; ni < 4; ni++)
            #pragma unroll
            for (int r = 0; r < 4; r++) acc[mi][ni][r] = 0.f;

    float4 pa[4], pb[4];

    auto stage = [&](int buf) {
        #pragma unroll
        for (int i = 0; i < 4; i++) {
            float4 v = pa[i];
            __nv_bfloat162 h0 = __floats2bfloat162_rn(v.x, v.y);
            __nv_bfloat162 h1 = __floats2bfloat162_rn(v.z, v.w);
            __nv_bfloat162 l0 = __floats2bfloat162_rn(v.x - __low2float(h0), v.y - __high2float(h0));
            __nv_bfloat162 l1 = __floats2bfloat162_rn(v.z - __low2float(h1), v.w - __high2float(h1));
            int off = buf * BM * ASTR + aR[i] * ASTR + aC[i];
            *reinterpret_cast<__nv_bfloat162*>(sAh + off)     = h0;
            *reinterpret_cast<__nv_bfloat162*>(sAh + off + 2) = h1;
            *reinterpret_cast<__nv_bfloat162*>(sAl + off)     = l0;
            *reinterpret_cast<__nv_bfloat162*>(sAl + off + 2) = l1;

            v = pb[i];
            h0 = __floats2bfloat162_rn(v.x, v.y);
            h1 = __floats2bfloat162_rn(v.z, v.w);
            l0 = __floats2bfloat162_rn(v.x - __low2float(h0), v.y - __high2float(h0));
            l1 = __floats2bfloat162_rn(v.z - __low2float(h1), v.w - __high2float(h1));
            off = buf * BKC * BSTR + bR[i] * BSTR + bC[i];
            *reinterpret_cast<__nv_bfloat162*>(sBh + off)     = h0;
            *reinterpret_cast<__nv_bfloat162*>(sBh + off + 2) = h1;
            *reinterpret_cast<__nv_bfloat162*>(sBl + off)     = l0;
            *reinterpret_cast<__nv_bfloat162*>(sBl + off + 2) = l1;
        }
    };

    // load + stage chunk 0
    #pragma unroll
    for (int i = 0; i < 4; i++) {
        pa[i] = *reinterpret_cast<const float4*>(A + (size_t)(row0 + aR[i]) * K + aC[i]);
        pb[i] = bval[i] ? *reinterpret_cast<const float4*>(B + (size_t)bR[i] * N + col0 + bC[i])
                        : make_float4(0.f, 0.f, 0.f, 0.f);
    }
    stage(0);
    __syncthreads();

    const int nChunks = K / BKC;
    for (int c = 0; c < nChunks; c++) {
        const int cur = c & 1;
        if (c + 1 < nChunks) {
            const int k0 = (c + 1) * BKC;
            #pragma unroll
            for (int i = 0; i < 4; i++) {
                pa[i] = *reinterpret_cast<const float4*>(A + (size_t)(row0 + aR[i]) * K + k0 + aC[i]);
                pb[i] = bval[i] ? *reinterpret_cast<const float4*>(B + (size_t)(k0 + bR[i]) * N + col0 + bC[i])
                                : make_float4(0.f, 0.f, 0.f, 0.f);
            }
        }

        const uint32_t ahB = sAh_u + (uint32_t)(cur * BM * ASTR * 2);
        const uint32_t alB = sAl_u + (uint32_t)(cur * BM * ASTR * 2);
        const uint32_t bhB = sBh_u + (uint32_t)(cur * BKC * BSTR * 2);
        const uint32_t blB = sBl_u + (uint32_t)(cur * BKC * BSTR * 2);

        #pragma unroll
        for (int ks = 0; ks < 2; ks++) {
            const int kb = ks * 16;
            uint32_t ah[4][4], al[4][4], bh[4][2], bl[4][2];
            #pragma unroll
            for (int mi = 0; mi < 4; mi++) {
                uint32_t off = (uint32_t)(((wm0 + mi * 16) * ASTR + kb) * 2) + aLane;
                ldsm_x4(ah[mi], ahB + off);
                ldsm_x4(al[mi], alB + off);
            }
            #pragma unroll
            for (int nj = 0; nj < 2; nj++) {
                uint32_t off = (uint32_t)((kb * BSTR + wn0 + nj * 16) * 2) + bLane;
                uint32_t t[4];
                ldsm_x4_t(t, bhB + off);
                bh[nj*2][0] = t[0]; bh[nj*2][1] = t[1]; bh[nj*2+1][0] = t[2]; bh[nj*2+1][1] = t[3];
                ldsm_x4_t(t, blB + off);
                bl[nj*2][0] = t[0]; bl[nj*2][1] = t[1]; bl[nj*2+1][0] = t[2]; bl[nj*2+1][1] = t[3];
            }
            #pragma unroll
            for (int mi = 0; mi < 4; mi++) {
                #pragma unroll
                for (int ni = 0; ni < 4; ni++) {
                    mma16816(acc[mi][ni], ah[mi], bh[ni]);
                    mma16816(acc[mi][ni], ah[mi], bl[ni]);
                    mma16816(acc[mi][ni], al[mi], bh[ni]);
                }
            }
        }

        if (c + 1 < nChunks) stage(cur ^ 1);
        __syncthreads();
    }

    // epilogue
    #pragma unroll
    for (int mi = 0; mi < 4; mi++) {
        #pragma unroll
        for (int ni = 0; ni < 4; ni++) {
            int r0 = row0 + wm0 + mi * 16 + (lane >> 2);
            int cc = col0 + wn0 + ni * 8 + (lane & 3) * 2;
            if (cc < N) {
                float2 v0 = make_float2(acc[mi][ni][0], acc[mi][ni][1]);
                float2 v1 = make_float2(acc[mi][ni][2], acc[mi][ni][3]);
                if (Res) {
                    float2 r0v = *reinterpret_cast<const float2*>(Res + (size_t)r0 * N + cc);
                    float2 r1v = *reinterpret_cast<const float2*>(Res + (size_t)(r0 + 8) * N + cc);
                    v0.x += r0v.x; v0.y += r0v.y; v1.x += r1v.x; v1.y += r1v.y;
                }
                *reinterpret_cast<float2*>(C + (size_t)r0 * N + cc) = v0;
                *reinterpret_cast<float2*>(C + (size_t)(r0 + 8) * N + cc) = v1;
            }
        }
    }
}

// ---------------- RoPE (interleaved: reference permutes even/odd first) ----------------
__global__ void rope_q_kernel(float* __restrict__ q,
                              const float* __restrict__ cosb, const float* __restrict__ sinb,
                              const int* __restrict__ pos)
{
    int s = blockIdx.x, h = blockIdx.y, j = threadIdx.x;  // j in [0,32)
    int p = pos[s];
    float* base = q + (size_t)s * (NH * QHD) + h * QHD + NOPE;
    float x0 = base[2 * j], x1 = base[2 * j + 1];
    float c0 = cosb[p * ROPE + j],      s0 = sinb[p * ROPE + j];
    float c1 = cosb[p * ROPE + 32 + j], s1 = sinb[p * ROPE + 32 + j];
    __syncwarp();
    base[j]      = x0 * c0 - x1 * s0;
    base[32 + j] = x1 * c1 + x0 * s1;
}

__global__ void rope_k_kernel(const float* __restrict__ ckv, float* __restrict__ kpe,
                              const float* __restrict__ cosb, const float* __restrict__ sinb,
                              const int* __restrict__ pos)
{
    int s = blockIdx.x, j = threadIdx.x;  // j in [0,32)
    int p = pos[s];
    const float* base = ckv + (size_t)s * (KVLR + ROPE) + KVLR;
    float x0 = base[2 * j], x1 = base[2 * j + 1];
    kpe[(size_t)s * ROPE + j]      = x0 * cosb[p * ROPE + j]      - x1 * sinb[p * ROPE + j];
    kpe[(size_t)s * ROPE + 32 + j] = x1 * cosb[p * ROPE + 32 + j] + x0 * sinb[p * ROPE + 32 + j];
}

// ---------------- Causal flash attention (fp32) ----------------
#define KSTR 196
__global__ __launch_bounds__(256) void attn_kernel(
    const float* __restrict__ Q,   // [S, NH*192]
    const float* __restrict__ KV,  // [S, NH*256] (k_nope | v)
    const float* __restrict__ KPE, // [S, 64]
    float* __restrict__ O)         // [S, NH*128]
{
    __shared__ float sQ[16][KSTR];
    __shared__ float sK[16][KSTR];
    __shared__ float sV[16][132];
    __shared__ float sS[16][17];

    const int h  = blockIdx.y;
    const int q0 = blockIdx.x * 16;
    const int tid = threadIdx.x;
    const int qi = tid >> 4, ki = tid & 15;
    const float sc = scale_const();

    for (int idx = tid; idx < 16 * 48; idx += 256) {
        int r = idx / 48, c = idx % 48;
        float4 v = *reinterpret_cast<const float4*>(Q + (size_t)(q0 + r) * (NH * QHD) + h * QHD + c * 4);
        v.x *= sc; v.y *= sc; v.z *= sc; v.w *= sc;
        *reinterpret_cast<float4*>(&sQ[r][c * 4]) = v;
    }
    float m = -1e30f, l = 0.f, acc[8];
    #pragma unroll
    for (int i = 0; i < 8; i++) acc[i] = 0.f;
    __syncthreads();

    for (int k0 = 0; k0 < q0 + 16; k0 += 16) {
        for (int idx = tid; idx < 16 * 48; idx += 256) {
            int r = idx / 48, c = idx % 48;
            float4 v;
            if (c < 32)
                v = *reinterpret_cast<const float4*>(KV + (size_t)(k0 + r) * (NH * 256) + h * 256 + c * 4);
            else
                v = *reinterpret_cast<const float4*>(KPE + (size_t)(k0 + r) * ROPE + (c - 32) * 4);
            *reinterpret_cast<float4*>(&sK[r][c * 4]) = v;
        }
        for (int idx = tid; idx < 16 * 32; idx += 256) {
            int r = idx / 32, c = idx % 32;
            *reinterpret_cast<float4*>(&sV[r][c * 4]) =
                *reinterpret_cast<const float4*>(KV + (size_t)(k0 + r) * (NH * 256) + h * 256 + 128 + c * 4);
        }
        __syncthreads();

        float s = 0.f;
        const float4* qp = reinterpret_cast<const float4*>(sQ[qi]);
        const float4* kp = reinterpret_cast<const float4*>(sK[ki]);
        #pragma unroll
        for (int d = 0; d < 48; d++) {
            float4 a = qp[d], b = kp[d];
            s = fmaf(a.x, b.x, s); s = fmaf(a.y, b.y, s);
            s = fmaf(a.z, b.z, s); s = fmaf(a.w, b.w, s);
        }
        if (k0 + ki > q0 + qi) s = -1e30f;
        sS[qi][ki] = s;
        __syncthreads();

        float tmax = -1e30f;
        #pragma unroll
        for (int k = 0; k < 16; k++) tmax = fmaxf(tmax, sS[qi][k]);
        float mnew  = fmaxf(m, tmax);
        float alpha = __expf(m - mnew);
        float pk[16], psum = 0.f;
        #pragma unroll
        for (int k = 0; k < 16; k++) { pk[k] = __expf(sS[qi][k] - mnew); psum += pk[k]; }
        l = l * alpha + psum;
        m = mnew;
        #pragma unroll
        for (int i = 0; i < 8; i++) acc[i] *= alpha;
        #pragma unroll
        for (int k = 0; k < 16; k++) {
            float p = pk[k];
            #pragma unroll
            for (int i = 0; i < 8; i++)
                acc[i] = fmaf(p, sV[k][ki * 8 + i], acc[i]);
        }
        __syncthreads();
    }

    float invl = 1.0f / l;
    #pragma unroll
    for (int i = 0; i < 8; i++)
        O[(size_t)(q0 + qi) * (NH * VHD) + h * VHD + ki * 8 + i] = acc[i] * invl;
}

// ---------------- SiLU(g) * u, in place into g ----------------
__global__ void silu_mul_kernel(float* __restrict__ g, const float* __restrict__ u, int n4)
{
    for (int i = blockIdx.x * blockDim.x + threadIdx.x; i < n4; i += gridDim.x * blockDim.x) {
        float4 a = reinterpret_cast<float4*>(g)[i];
        float4 b = reinterpret_cast<const float4*>(u)[i];
        a.x = (a.x / (1.f + __expf(-a.x))) * b.x;
        a.y = (a.y / (1.f + __expf(-a.y))) * b.y;
        a.z = (a.z / (1.f + __expf(-a.z))) * b.z;
        a.w = (a.w / (1.f + __expf(-a.w))) * b.w;
        reinterpret_cast<float4*>(g)[i] = a;
    }
}

// ---------------- Host orchestration ----------------
static void gemm(const float* A, const float* B, const float* Res, float* C, int M, int N, int K)
{
    cudaFuncSetAttribute(mma_gemm_kernel, cudaFuncAttributeMaxDynamicSharedMemorySize, GEMM_SMEM_BYTES);
    dim3 grid((N + 127) / 128, (M + 127) / 128);
    mma_gemm_kernel<<<grid, 256, GEMM_SMEM_BYTES>>>(A, B, Res, C, M, N, K);
}

extern "C" void kernel_launch(void* const* d_in, const int* in_sizes, int n_in,
                              void* d_out, int out_size)
{
    const float* hidden  = (const float*)d_in[0];
    const float* sinb    = (const float*)d_in[1];
    const float* cosb    = (const float*)d_in[2];
    const float* wq_a    = (const float*)d_in[3];
    const float* q_a_ln  = (const float*)d_in[4];
    const float* wq_b    = (const float*)d_in[5];
    const float* wkv_a   = (const float*)d_in[6];
    const float* kv_a_ln = (const float*)d_in[7];
    const float* wkv_b   = (const float*)d_in[8];
    const float* wo      = (const float*)d_in[9];
    const float* in_ln   = (const float*)d_in[10];
    const float* post_ln = (const float*)d_in[11];
    const float* w_gate  = (const float*)d_in[12];
    const float* w_up    = (const float*)d_in[13];
    const float* w_down  = (const float*)d_in[14];
    const int*   pos     = (const int*)d_in[15];
    float* out = (float*)d_out;

    float *xn, *qlat, *qb, *ckv, *ckvn, *kpe, *kv, *ao, *h2, *y, *gb, *ub;
    cudaGetSymbolAddress((void**)&xn,   g_xn);
    cudaGetSymbolAddress((void**)&qlat, g_qlat);
    cudaGetSymbolAddress((void**)&qb,   g_q);
    cudaGetSymbolAddress((void**)&ckv,  g_ckv);
    cudaGetSymbolAddress((void**)&ckvn, g_ckvn);
    cudaGetSymbolAddress((void**)&kpe,  g_kpe);
    cudaGetSymbolAddress((void**)&kv,   g_kv);
    cudaGetSymbolAddress((void**)&ao,   g_ao);
    cudaGetSymbolAddress((void**)&h2,   g_h2);
    cudaGetSymbolAddress((void**)&y,    g_y);
    cudaGetSymbolAddress((void**)&gb,   g_g);
    cudaGetSymbolAddress((void**)&ub,   g_u);

    // 1) input RMSNorm
    rms_kernel<<<S_LEN, 256>>>(hidden, in_ln, xn, HDIM, HDIM, HDIM);
    // 2) q low-rank path
    gemm(xn, wq_a, nullptr, qlat, S_LEN, QLR, HDIM);
    rms_kernel<<<S_LEN, 256>>>(qlat, q_a_ln, qlat, QLR, QLR, QLR);
    gemm(qlat, wq_b, nullptr, qb, S_LEN, NH * QHD, QLR);
    // 3) kv low-rank path
    gemm(xn, wkv_a, nullptr, ckv, S_LEN, KVLR + ROPE, HDIM);
    rms_kernel<<<S_LEN, 256>>>(ckv, kv_a_ln, ckvn, KVLR, KVLR + ROPE, KVLR);
    rope_k_kernel<<<S_LEN, 32>>>(ckv, kpe, cosb, sinb, pos);
    gemm(ckvn, wkv_b, nullptr, kv, S_LEN, NH * (NOPE + VHD), KVLR);
    // 4) rope on q_pe (in place)
    rope_q_kernel<<<dim3(S_LEN, NH), 32>>>(qb, cosb, sinb, pos);
    // 5) attention
    attn_kernel<<<dim3(S_LEN / 16, NH), 256>>>(qb, kv, kpe, ao);
    // 6) output projection + residual
    gemm(ao, wo, hidden, h2, S_LEN, HDIM, NH * VHD);
    // 7) MLP
    rms_kernel<<<S_LEN, 256>>>(h2, post_ln, y, HDIM, HDIM, HDIM);
    gemm(y, w_gate, nullptr, gb, S_LEN, FF, HDIM);
    gemm(y, w_up,   nullptr, ub, S_LEN, FF, HDIM);
    silu_mul_kernel<<<4096, 256>>>(gb, ub, (S_LEN * FF) / 4);
    gemm(gb, w_down, h2, out, S_LEN, HDIM, FF);
}

// round 6
// speedup vs baseline: 2.0977x; 1.0746x over previous
#include <cuda_runtime.h>
#include <cuda_bf16.h>
#include <cstdint>
#include <cstddef>

// ---------------- Problem constants ----------------
#define S_LEN 2048
#define HDIM  2048
#define NH    16
#define NOPE  128
#define ROPE  64
#define VHD   128
#define QHD   192
#define QLR   1536
#define KVLR  512
#define FF    8192
#define EPS_F 1e-6f
static __device__ __host__ __forceinline__ float scale_const() { return 0.07216878364870323f; } // 192^-0.5

typedef __nv_bfloat16 bf16;

// ---------------- fp32 scratch ----------------
__device__ float g_qlat[S_LEN * QLR];
__device__ float g_q   [S_LEN * NH * QHD];
__device__ float g_ckv [S_LEN * (KVLR+ROPE)];
__device__ float g_kpe [S_LEN * ROPE];
__device__ float g_kv  [S_LEN * NH * (NOPE+VHD)];
__device__ float g_h2  [S_LEN * HDIM];
__device__ float g_g   [S_LEN * FF];
__device__ float g_u   [S_LEN * FF];

// ---------------- bf16 hi/lo scratch: weights ----------------
__device__ bf16 w_qa_h[HDIM*QLR],        w_qa_l[HDIM*QLR];
__device__ bf16 w_qb_h[QLR*NH*QHD],      w_qb_l[QLR*NH*QHD];
__device__ bf16 w_kva_h[HDIM*(KVLR+ROPE)], w_kva_l[HDIM*(KVLR+ROPE)];
__device__ bf16 w_kvb_h[KVLR*NH*(NOPE+VHD)], w_kvb_l[KVLR*NH*(NOPE+VHD)];
__device__ bf16 w_o_h[NH*VHD*HDIM],      w_o_l[NH*VHD*HDIM];
__device__ bf16 w_g_h[HDIM*FF],          w_g_l[HDIM*FF];
__device__ bf16 w_u_h[HDIM*FF],          w_u_l[HDIM*FF];
__device__ bf16 w_d_h[FF*HDIM],          w_d_l[FF*HDIM];
// ---------------- bf16 hi/lo scratch: activations ----------------
__device__ bf16 a_xn_h[S_LEN*HDIM],   a_xn_l[S_LEN*HDIM];
__device__ bf16 a_ql_h[S_LEN*QLR],    a_ql_l[S_LEN*QLR];
__device__ bf16 a_ckv_h[S_LEN*KVLR],  a_ckv_l[S_LEN*KVLR];
__device__ bf16 a_ao_h[S_LEN*NH*VHD], a_ao_l[S_LEN*NH*VHD];
__device__ bf16 a_y_h[S_LEN*HDIM],    a_y_l[S_LEN*HDIM];
__device__ bf16 a_gb_h[S_LEN*FF],     a_gb_l[S_LEN*FF];

// ---------------- helpers ----------------
static __device__ __forceinline__ uint32_t smem_u32(const void* p) {
    return (uint32_t)__cvta_generic_to_shared(p);
}
static __device__ __forceinline__ void cp16(uint32_t dst, const void* src, uint32_t sz) {
    asm volatile("cp.async.cg.shared.global [%0], [%1], 16, %2;" :: "r"(dst), "l"(src), "r"(sz));
}
static __device__ __forceinline__ void cp_commit() { asm volatile("cp.async.commit_group;"); }
static __device__ __forceinline__ void cp_wait0()  { asm volatile("cp.async.wait_group 0;"); }
static __device__ __forceinline__ void ldsm_x4(uint32_t* r, uint32_t addr) {
    asm volatile("ldmatrix.sync.aligned.m8n8.x4.shared.b16 {%0,%1,%2,%3}, [%4];"
                 : "=r"(r[0]), "=r"(r[1]), "=r"(r[2]), "=r"(r[3]) : "r"(addr));
}
static __device__ __forceinline__ void ldsm_x4_t(uint32_t* r, uint32_t addr) {
    asm volatile("ldmatrix.sync.aligned.m8n8.x4.trans.shared.b16 {%0,%1,%2,%3}, [%4];"
                 : "=r"(r[0]), "=r"(r[1]), "=r"(r[2]), "=r"(r[3]) : "r"(addr));
}
static __device__ __forceinline__ void mma16816(float* c, const uint32_t* a, const uint32_t* b) {
    asm volatile("mma.sync.aligned.m16n8k16.row.col.f32.bf16.bf16.f32 "
                 "{%0,%1,%2,%3}, {%4,%5,%6,%7}, {%8,%9}, {%0,%1,%2,%3};"
                 : "+f"(c[0]), "+f"(c[1]), "+f"(c[2]), "+f"(c[3])
                 : "r"(a[0]), "r"(a[1]), "r"(a[2]), "r"(a[3]), "r"(b[0]), "r"(b[1]));
}
static __device__ __forceinline__ void split1(float x, bf16& h, bf16& l) {
    h = __float2bfloat16(x);
    l = __float2bfloat16(x - __bfloat162float(h));
}

// ---------------- weight split conversion ----------------
__global__ __launch_bounds__(256) void convert_split_kernel(
    const float* __restrict__ in, bf16* __restrict__ hi, bf16* __restrict__ lo, int n4)
{
    for (int i = blockIdx.x * blockDim.x + threadIdx.x; i < n4; i += gridDim.x * blockDim.x) {
        float4 v = reinterpret_cast<const float4*>(in)[i];
        bf16 h0,l0,h1,l1,h2,l2,h3,l3;
        split1(v.x,h0,l0); split1(v.y,h1,l1); split1(v.z,h2,l2); split1(v.w,h3,l3);
        __nv_bfloat162* hp = reinterpret_cast<__nv_bfloat162*>(hi) + 2*i;
        __nv_bfloat162* lp = reinterpret_cast<__nv_bfloat162*>(lo) + 2*i;
        hp[0] = __nv_bfloat162(h0,h1); hp[1] = __nv_bfloat162(h2,h3);
        lp[0] = __nv_bfloat162(l0,l1); lp[1] = __nv_bfloat162(l2,l3);
    }
}

// ---------------- RMSNorm -> bf16 hi/lo ----------------
__global__ __launch_bounds__(256) void rms_split_kernel(
    const float* __restrict__ in, const float* __restrict__ w,
    bf16* __restrict__ hi, bf16* __restrict__ lo, int cols, int in_stride)
{
    int row = blockIdx.x;
    const float* ip = in + (size_t)row * in_stride;
    float ss = 0.f;
    for (int i = threadIdx.x; i < cols; i += 256) { float v = ip[i]; ss = fmaf(v, v, ss); }
    __shared__ float sh[8];
    int lane = threadIdx.x & 31, wid = threadIdx.x >> 5;
    #pragma unroll
    for (int o = 16; o > 0; o >>= 1) ss += __shfl_xor_sync(0xffffffffu, ss, o);
    if (lane == 0) sh[wid] = ss;
    __syncthreads();
    float tot = 0.f;
    #pragma unroll
    for (int i = 0; i < 8; i++) tot += sh[i];
    float r = rsqrtf(tot / (float)cols + EPS_F);
    bf16* hp = hi + (size_t)row * cols;
    bf16* lp = lo + (size_t)row * cols;
    for (int i = threadIdx.x; i < cols; i += 256) {
        float v = ip[i] * r * w[i];
        bf16 h, l; split1(v, h, l);
        hp[i] = h; lp[i] = l;
    }
}

// ---------------- Tensor-core GEMM: bf16 hi/lo inputs, fp32 out ----------------
// BM=BN=128, BK=32, 128 threads (4 warps, 64x64 warp tiles), 2-stage cp.async.
#define ASTR 40
#define BSTR 136
#define A_ST (128*ASTR)                 // bf16 elems per A matrix per stage
#define B_ST (32*BSTR)
#define STAGE_ELEMS (2*A_ST + 2*B_ST)   // 18944
#define GEMM_SMEM_BYTES (2*STAGE_ELEMS*2)  // 75776

__global__ __launch_bounds__(128, 2) void mma_gemm2_kernel(
    const bf16* __restrict__ Ah, const bf16* __restrict__ Al,
    const bf16* __restrict__ Bh, const bf16* __restrict__ Bl,
    const float* __restrict__ Res, float* __restrict__ C,
    int M, int N, int K)
{
    extern __shared__ bf16 sm[];
    const int tid  = threadIdx.x;
    const int lane = tid & 31;
    const int warp = tid >> 5;
    const int wm0  = (warp >> 1) * 64;
    const int wn0  = (warp & 1) * 64;
    const int row0 = blockIdx.y * 128;
    const int col0 = blockIdx.x * 128;
    const uint32_t smu = smem_u32(sm);

    // staging coords: 512 16B-chunks per matrix, 4 per thread
    int aRow[4], aCol[4], bRow[4], bCol[4];
    uint32_t bSz[4];
    #pragma unroll
    for (int i = 0; i < 4; i++) {
        int lin = tid + 128 * i;
        aRow[i] = lin >> 2;  aCol[i] = (lin & 3) * 8;
        bRow[i] = lin >> 4;  bCol[i] = (lin & 15) * 8;
        bSz[i]  = (col0 + bCol[i]) < N ? 16u : 0u;
    }
    const uint32_t aLane = (uint32_t)(((lane & 15) * ASTR + (lane >> 4) * 8) * 2);
    const uint32_t bLane = (uint32_t)(((lane & 15) * BSTR + (lane >> 4) * 8) * 2);

    float acc[4][8][4];
    #pragma unroll
    for (int mi = 0; mi < 4; mi++)
        #pragma unroll
        for (int ni = 0; ni < 8; ni++)
            #pragma unroll
            for (int r = 0; r < 4; r++) acc[mi][ni][r] = 0.f;

    auto stage = [&](int kk, int buf) {
        uint32_t base = smu + (uint32_t)(buf * STAGE_ELEMS * 2);
        #pragma unroll
        for (int i = 0; i < 4; i++) {
            uint32_t ad = base + (uint32_t)((aRow[i] * ASTR + aCol[i]) * 2);
            const bf16* asrc = Ah + (size_t)(row0 + aRow[i]) * K + kk + aCol[i];
            const bf16* asrc2 = Al + (size_t)(row0 + aRow[i]) * K + kk + aCol[i];
            cp16(ad, asrc, 16);
            cp16(ad + (uint32_t)(A_ST * 2), asrc2, 16);
            int bc = col0 + bCol[i]; if (bc > N - 8) bc = N - 8;
            uint32_t bd = base + (uint32_t)(2 * A_ST * 2 + (bRow[i] * BSTR + bCol[i]) * 2);
            const bf16* bsrc = Bh + (size_t)(kk + bRow[i]) * N + bc;
            const bf16* bsrc2 = Bl + (size_t)(kk + bRow[i]) * N + bc;
            cp16(bd, bsrc, bSz[i]);
            cp16(bd + (uint32_t)(B_ST * 2), bsrc2, bSz[i]);
        }
        cp_commit();
    };

    stage(0, 0);
    cp_wait0();
    __syncthreads();

    const int nChunks = K / 32;
    for (int c = 0; c < nChunks; c++) {
        const int cur = c & 1;
        if (c + 1 < nChunks) stage((c + 1) * 32, cur ^ 1);

        const uint32_t ahB = smu + (uint32_t)(cur * STAGE_ELEMS * 2);
        const uint32_t alB = ahB + (uint32_t)(A_ST * 2);
        const uint32_t bhB = ahB + (uint32_t)(2 * A_ST * 2);
        const uint32_t blB = bhB + (uint32_t)(B_ST * 2);

        #pragma unroll
        for (int ks = 0; ks < 2; ks++) {
            const int kb = ks * 16;
            uint32_t ah[4][4], al[4][4], bh[8][2], bl[8][2];
            #pragma unroll
            for (int mi = 0; mi < 4; mi++) {
                uint32_t off = (uint32_t)(((wm0 + mi * 16) * ASTR + kb) * 2) + aLane;
                ldsm_x4(ah[mi], ahB + off);
                ldsm_x4(al[mi], alB + off);
            }
            #pragma unroll
            for (int nj = 0; nj < 4; nj++) {
                uint32_t off = (uint32_t)((kb * BSTR + wn0 + nj * 16) * 2) + bLane;
                uint32_t t[4];
                ldsm_x4_t(t, bhB + off);
                bh[nj*2][0] = t[0]; bh[nj*2][1] = t[1]; bh[nj*2+1][0] = t[2]; bh[nj*2+1][1] = t[3];
                ldsm_x4_t(t, blB + off);
                bl[nj*2][0] = t[0]; bl[nj*2][1] = t[1]; bl[nj*2+1][0] = t[2]; bl[nj*2+1][1] = t[3];
            }
            #pragma unroll
            for (int mi = 0; mi < 4; mi++) {
                #pragma unroll
                for (int ni = 0; ni < 8; ni++) {
                    mma16816(acc[mi][ni], ah[mi], bh[ni]);
                    mma16816(acc[mi][ni], ah[mi], bl[ni]);
                    mma16816(acc[mi][ni], al[mi], bh[ni]);
                }
            }
        }

        if (c + 1 < nChunks) cp_wait0();
        __syncthreads();
    }

    // epilogue
    #pragma unroll
    for (int mi = 0; mi < 4; mi++) {
        #pragma unroll
        for (int ni = 0; ni < 8; ni++) {
            int r0 = row0 + wm0 + mi * 16 + (lane >> 2);
            int cc = col0 + wn0 + ni * 8 + (lane & 3) * 2;
            if (cc < N) {
                float2 v0 = make_float2(acc[mi][ni][0], acc[mi][ni][1]);
                float2 v1 = make_float2(acc[mi][ni][2], acc[mi][ni][3]);
                if (Res) {
                    float2 r0v = *reinterpret_cast<const float2*>(Res + (size_t)r0 * N + cc);
                    float2 r1v = *reinterpret_cast<const float2*>(Res + (size_t)(r0 + 8) * N + cc);
                    v0.x += r0v.x; v0.y += r0v.y; v1.x += r1v.x; v1.y += r1v.y;
                }
                *reinterpret_cast<float2*>(C + (size_t)r0 * N + cc) = v0;
                *reinterpret_cast<float2*>(C + (size_t)(r0 + 8) * N + cc) = v1;
            }
        }
    }
}

// ---------------- RoPE ----------------
__global__ void rope_q_kernel(float* __restrict__ q,
                              const float* __restrict__ cosb, const float* __restrict__ sinb,
                              const int* __restrict__ pos)
{
    int s = blockIdx.x, h = blockIdx.y, j = threadIdx.x;
    int p = pos[s];
    float* base = q + (size_t)s * (NH * QHD) + h * QHD + NOPE;
    float x0 = base[2 * j], x1 = base[2 * j + 1];
    float c0 = cosb[p * ROPE + j],      s0 = sinb[p * ROPE + j];
    float c1 = cosb[p * ROPE + 32 + j], s1 = sinb[p * ROPE + 32 + j];
    __syncwarp();
    base[j]      = x0 * c0 - x1 * s0;
    base[32 + j] = x1 * c1 + x0 * s1;
}

__global__ void rope_k_kernel(const float* __restrict__ ckv, float* __restrict__ kpe,
                              const float* __restrict__ cosb, const float* __restrict__ sinb,
                              const int* __restrict__ pos)
{
    int s = blockIdx.x, j = threadIdx.x;
    int p = pos[s];
    const float* base = ckv + (size_t)s * (KVLR + ROPE) + KVLR;
    float x0 = base[2 * j], x1 = base[2 * j + 1];
    kpe[(size_t)s * ROPE + j]      = x0 * cosb[p * ROPE + j]      - x1 * sinb[p * ROPE + j];
    kpe[(size_t)s * ROPE + 32 + j] = x1 * cosb[p * ROPE + 32 + j] + x0 * sinb[p * ROPE + 32 + j];
}

// ---------------- Causal flash attention (fp32), bf16 hi/lo output ----------------
#define KSTR 196
__global__ __launch_bounds__(256) void attn_kernel(
    const float* __restrict__ Q,
    const float* __restrict__ KV,
    const float* __restrict__ KPE,
    bf16* __restrict__ Oh, bf16* __restrict__ Ol)
{
    __shared__ float sQ[16][KSTR];
    __shared__ float sK[16][KSTR];
    __shared__ float sV[16][132];
    __shared__ float sS[16][17];

    const int h  = blockIdx.y;
    const int q0 = blockIdx.x * 16;
    const int tid = threadIdx.x;
    const int qi = tid >> 4, ki = tid & 15;
    const float sc = scale_const();

    for (int idx = tid; idx < 16 * 48; idx += 256) {
        int r = idx / 48, c = idx % 48;
        float4 v = *reinterpret_cast<const float4*>(Q + (size_t)(q0 + r) * (NH * QHD) + h * QHD + c * 4);
        v.x *= sc; v.y *= sc; v.z *= sc; v.w *= sc;
        *reinterpret_cast<float4*>(&sQ[r][c * 4]) = v;
    }
    float m = -1e30f, l = 0.f, acc[8];
    #pragma unroll
    for (int i = 0; i < 8; i++) acc[i] = 0.f;
    __syncthreads();

    for (int k0 = 0; k0 < q0 + 16; k0 += 16) {
        for (int idx = tid; idx < 16 * 48; idx += 256) {
            int r = idx / 48, c = idx % 48;
            float4 v;
            if (c < 32)
                v = *reinterpret_cast<const float4*>(KV + (size_t)(k0 + r) * (NH * 256) + h * 256 + c * 4);
            else
                v = *reinterpret_cast<const float4*>(KPE + (size_t)(k0 + r) * ROPE + (c - 32) * 4);
            *reinterpret_cast<float4*>(&sK[r][c * 4]) = v;
        }
        for (int idx = tid; idx < 16 * 32; idx += 256) {
            int r = idx / 32, c = idx % 32;
            *reinterpret_cast<float4*>(&sV[r][c * 4]) =
                *reinterpret_cast<const float4*>(KV + (size_t)(k0 + r) * (NH * 256) + h * 256 + 128 + c * 4);
        }
        __syncthreads();

        float s = 0.f;
        const float4* qp = reinterpret_cast<const float4*>(sQ[qi]);
        const float4* kp = reinterpret_cast<const float4*>(sK[ki]);
        #pragma unroll
        for (int d = 0; d < 48; d++) {
            float4 a = qp[d], b = kp[d];
            s = fmaf(a.x, b.x, s); s = fmaf(a.y, b.y, s);
            s = fmaf(a.z, b.z, s); s = fmaf(a.w, b.w, s);
        }
        if (k0 + ki > q0 + qi) s = -1e30f;
        sS[qi][ki] = s;
        __syncthreads();

        float tmax = -1e30f;
        #pragma unroll
        for (int k = 0; k < 16; k++) tmax = fmaxf(tmax, sS[qi][k]);
        float mnew  = fmaxf(m, tmax);
        float alpha = __expf(m - mnew);
        float pk[16], psum = 0.f;
        #pragma unroll
        for (int k = 0; k < 16; k++) { pk[k] = __expf(sS[qi][k] - mnew); psum += pk[k]; }
        l = l * alpha + psum;
        m = mnew;
        #pragma unroll
        for (int i = 0; i < 8; i++) acc[i] *= alpha;
        #pragma unroll
        for (int k = 0; k < 16; k++) {
            float p = pk[k];
            #pragma unroll
            for (int i = 0; i < 8; i++)
                acc[i] = fmaf(p, sV[k][ki * 8 + i], acc[i]);
        }
        __syncthreads();
    }

    float invl = 1.0f / l;
    size_t ob = (size_t)(q0 + qi) * (NH * VHD) + h * VHD + ki * 8;
    #pragma unroll
    for (int i = 0; i < 8; i++) {
        float v = acc[i] * invl;
        bf16 hh, ll; split1(v, hh, ll);
        Oh[ob + i] = hh; Ol[ob + i] = ll;
    }
}

// ---------------- SiLU(g)*u -> bf16 hi/lo ----------------
__global__ void silu_split_kernel(const float* __restrict__ g, const float* __restrict__ u,
                                  bf16* __restrict__ hi, bf16* __restrict__ lo, int n4)
{
    for (int i = blockIdx.x * blockDim.x + threadIdx.x; i < n4; i += gridDim.x * blockDim.x) {
        float4 a = reinterpret_cast<const float4*>(g)[i];
        float4 b = reinterpret_cast<const float4*>(u)[i];
        a.x = (a.x / (1.f + __expf(-a.x))) * b.x;
        a.y = (a.y / (1.f + __expf(-a.y))) * b.y;
        a.z = (a.z / (1.f + __expf(-a.z))) * b.z;
        a.w = (a.w / (1.f + __expf(-a.w))) * b.w;
        bf16 h0,l0,h1,l1,h2,l2,h3,l3;
        split1(a.x,h0,l0); split1(a.y,h1,l1); split1(a.z,h2,l2); split1(a.w,h3,l3);
        __nv_bfloat162* hp = reinterpret_cast<__nv_bfloat162*>(hi) + 2*i;
        __nv_bfloat162* lp = reinterpret_cast<__nv_bfloat162*>(lo) + 2*i;
        hp[0] = __nv_bfloat162(h0,h1); hp[1] = __nv_bfloat162(h2,h3);
        lp[0] = __nv_bfloat162(l0,l1); lp[1] = __nv_bfloat162(l2,l3);
    }
}

// ---------------- Host orchestration ----------------
static void gemm2(const bf16* Ah, const bf16* Al, const bf16* Bh, const bf16* Bl,
                  const float* Res, float* C, int M, int N, int K)
{
    cudaFuncSetAttribute(mma_gemm2_kernel, cudaFuncAttributeMaxDynamicSharedMemorySize, GEMM_SMEM_BYTES);
    dim3 grid((N + 127) / 128, (M + 127) / 128);
    mma_gemm2_kernel<<<grid, 128, GEMM_SMEM_BYTES>>>(Ah, Al, Bh, Bl, Res, C, M, N, K);
}
static void convert_w(const float* w, bf16* h, bf16* l, int n)
{
    convert_split_kernel<<<1024, 256>>>(w, h, l, n / 4);
}

#define SYM(p, s) cudaGetSymbolAddress((void**)&p, s)

extern "C" void kernel_launch(void* const* d_in, const int* in_sizes, int n_in,
                              void* d_out, int out_size)
{
    const float* hidden  = (const float*)d_in[0];
    const float* sinb    = (const float*)d_in[1];
    const float* cosb    = (const float*)d_in[2];
    const float* wq_a    = (const float*)d_in[3];
    const float* q_a_ln  = (const float*)d_in[4];
    const float* wq_b    = (const float*)d_in[5];
    const float* wkv_a   = (const float*)d_in[6];
    const float* kv_a_ln = (const float*)d_in[7];
    const float* wkv_b   = (const float*)d_in[8];
    const float* wo      = (const float*)d_in[9];
    const float* in_ln   = (const float*)d_in[10];
    const float* post_ln = (const float*)d_in[11];
    const float* w_gate  = (const float*)d_in[12];
    const float* w_up    = (const float*)d_in[13];
    const float* w_down  = (const float*)d_in[14];
    const int*   pos     = (const int*)d_in[15];
    float* out = (float*)d_out;

    float *qlat, *qb, *ckv, *kpe, *kv, *h2, *gbuf, *ubuf;
    SYM(qlat, g_qlat); SYM(qb, g_q); SYM(ckv, g_ckv); SYM(kpe, g_kpe);
    SYM(kv, g_kv); SYM(h2, g_h2); SYM(gbuf, g_g); SYM(ubuf, g_u);

    bf16 *qa_h,*qa_l,*qbw_h,*qbw_l,*kva_h,*kva_l,*kvb_h,*kvb_l,*o_h,*o_l,*gw_h,*gw_l,*uw_h,*uw_l,*dw_h,*dw_l;
    SYM(qa_h, w_qa_h); SYM(qa_l, w_qa_l); SYM(qbw_h, w_qb_h); SYM(qbw_l, w_qb_l);
    SYM(kva_h, w_kva_h); SYM(kva_l, w_kva_l); SYM(kvb_h, w_kvb_h); SYM(kvb_l, w_kvb_l);
    SYM(o_h, w_o_h); SYM(o_l, w_o_l); SYM(gw_h, w_g_h); SYM(gw_l, w_g_l);
    SYM(uw_h, w_u_h); SYM(uw_l, w_u_l); SYM(dw_h, w_d_h); SYM(dw_l, w_d_l);

    bf16 *xn_h,*xn_l,*ql_h,*ql_l,*ckvn_h,*ckvn_l,*ao_h,*ao_l,*y_h,*y_l,*gb_h,*gb_l;
    SYM(xn_h, a_xn_h); SYM(xn_l, a_xn_l); SYM(ql_h, a_ql_h); SYM(ql_l, a_ql_l);
    SYM(ckvn_h, a_ckv_h); SYM(ckvn_l, a_ckv_l); SYM(ao_h, a_ao_h); SYM(ao_l, a_ao_l);
    SYM(y_h, a_y_h); SYM(y_l, a_y_l); SYM(gb_h, a_gb_h); SYM(gb_l, a_gb_l);

    // weight conversions
    convert_w(wq_a,  qa_h,  qa_l,  HDIM * QLR);
    convert_w(wq_b,  qbw_h, qbw_l, QLR * NH * QHD);
    convert_w(wkv_a, kva_h, kva_l, HDIM * (KVLR + ROPE));
    convert_w(wkv_b, kvb_h, kvb_l, KVLR * NH * (NOPE + VHD));
    convert_w(wo,    o_h,   o_l,   NH * VHD * HDIM);
    convert_w(w_gate, gw_h, gw_l,  HDIM * FF);
    convert_w(w_up,   uw_h, uw_l,  HDIM * FF);
    convert_w(w_down, dw_h, dw_l,  FF * HDIM);

    // 1) input RMSNorm -> bf16 hi/lo
    rms_split_kernel<<<S_LEN, 256>>>(hidden, in_ln, xn_h, xn_l, HDIM, HDIM);
    // 2) q path
    gemm2(xn_h, xn_l, qa_h, qa_l, nullptr, qlat, S_LEN, QLR, HDIM);
    rms_split_kernel<<<S_LEN, 256>>>(qlat, q_a_ln, ql_h, ql_l, QLR, QLR);
    gemm2(ql_h, ql_l, qbw_h, qbw_l, nullptr, qb, S_LEN, NH * QHD, QLR);
    // 3) kv path
    gemm2(xn_h, xn_l, kva_h, kva_l, nullptr, ckv, S_LEN, KVLR + ROPE, HDIM);
    rms_split_kernel<<<S_LEN, 256>>>(ckv, kv_a_ln, ckvn_h, ckvn_l, KVLR, KVLR + ROPE);
    rope_k_kernel<<<S_LEN, 32>>>(ckv, kpe, cosb, sinb, pos);
    gemm2(ckvn_h, ckvn_l, kvb_h, kvb_l, nullptr, kv, S_LEN, NH * (NOPE + VHD), KVLR);
    // 4) rope q
    rope_q_kernel<<<dim3(S_LEN, NH), 32>>>(qb, cosb, sinb, pos);
    // 5) attention -> bf16 hi/lo
    attn_kernel<<<dim3(S_LEN / 16, NH), 256>>>(qb, kv, kpe, ao_h, ao_l);
    // 6) output projection + residual
    gemm2(ao_h, ao_l, o_h, o_l, hidden, h2, S_LEN, HDIM, NH * VHD);
    // 7) MLP
    rms_split_kernel<<<S_LEN, 256>>>(h2, post_ln, y_h, y_l, HDIM, HDIM);
    gemm2(y_h, y_l, gw_h, gw_l, nullptr, gbuf, S_LEN, FF, HDIM);
    gemm2(y_h, y_l, uw_h, uw_l, nullptr, ubuf, S_LEN, FF, HDIM);
    silu_split_kernel<<<4096, 256>>>(gbuf, ubuf, gb_h, gb_l, (S_LEN * FF) / 4);
    gemm2(gb_h, gb_l, dw_h, dw_l, h2, out, S_LEN, HDIM, FF);
}